// round 7
// baseline (speedup 1.0000x reference)
#include <cuda_runtime.h>
#include <cooperative_groups.h>
#include <math.h>

namespace cg = cooperative_groups;

// Problem constants
#define NB      32          // batch N
#define D_IN    513         // S+1
#define TOTAL   262917      // per-(t,n) output row length
#define P_OFF   260
#define M_OFF   261
#define MN_OFF  262405
#define M_PER_N 262144      // S * ND * H

// Scratch (device globals — no allocation allowed)
__device__ float g_M [NB * M_PER_N];   // [n][s*512 + d*256 + h]
__device__ float g_Mn[NB * 512];       // [n][d*256 + h]
__device__ float g_loc[NB];
__device__ float g_v  [NB];
__device__ int   g_nonzero;

// ---------------- small PTX helpers ----------------
__device__ __forceinline__ unsigned long long ffma2(unsigned long long a,
                                                    unsigned long long b,
                                                    unsigned long long c) {
    unsigned long long d;
    asm("fma.rn.f32x2 %0, %1, %2, %3;" : "=l"(d) : "l"(a), "l"(b), "l"(c));
    return d;
}
union F2U { unsigned long long u; float2 f; };

__device__ __forceinline__ void mbar_init(unsigned addr, unsigned count) {
    asm volatile("mbarrier.init.shared.b64 [%0], %1;" :: "r"(addr), "r"(count) : "memory");
}
__device__ __forceinline__ void mbar_wait_cluster(unsigned addr, unsigned parity) {
    asm volatile(
        "{\n\t.reg .pred P1;\n\t"
        "LAB_%=:\n\t"
        "mbarrier.try_wait.parity.acquire.cluster.shared::cta.b64 P1, [%0], %1, 0x989680;\n\t"
        "@P1 bra DONE_%=;\n\t"
        "bra LAB_%=;\n\t"
        "DONE_%=:\n\t}"
        :: "r"(addr), "r"(parity) : "memory");
}
__device__ __forceinline__ void st_remote(unsigned laddr, unsigned rank, float v) {
    asm volatile(
        "{\n\t.reg .b32 ra;\n\t"
        "mapa.shared::cluster.u32 ra, %0, %1;\n\t"
        "st.shared::cluster.f32 [ra], %2;\n\t}"
        :: "r"(laddr), "r"(rank), "f"(v) : "memory");
}
__device__ __forceinline__ void arrive_remote(unsigned lmbar, unsigned rank) {
    asm volatile(
        "{\n\t.reg .b32 rm;\n\t"
        "mapa.shared::cluster.u32 rm, %0, %1;\n\t"
        "mbarrier.arrive.release.cluster.shared::cluster.b64 _, [rm];\n\t}"
        :: "r"(lmbar), "r"(rank) : "memory");
}

// ---------------- flag kernels ----------------
__global__ void reset_flag_kernel() { g_nonzero = 0; }

__global__ void scan_flag_kernel(const float* __restrict__ rnn) {
    const int NV4 = (NB * TOTAL) / 4;
    const float4* p = reinterpret_cast<const float4*>(rnn);
    bool nz = false;
    for (int i = blockIdx.x * blockDim.x + threadIdx.x; i < NV4; i += gridDim.x * blockDim.x) {
        float4 v = p[i];
        nz |= (v.x != 0.f) | (v.y != 0.f) | (v.z != 0.f) | (v.w != 0.f);
    }
    if (__syncthreads_or(nz) && threadIdx.x == 0) atomicOr(&g_nonzero, 1);
    if (threadIdx.x == 0 && blockIdx.x == 0) {
        // tail (TOTAL*NB divisible by 4? 8413344/4 = 2103336 exact, no tail)
    }
}

// ---------------- GRU cluster kernel ----------------
// grid (8, 8, 2): x = cluster rank (32-col slice of h), y = n-group (4 n), z = direction.
// Cluster of 8 CTAs shares h state of its 4 batch rows via DSMEM push + parity mbarriers.
// Thread layout: tid = rr*4 + q, rr = gate row 0..95 (within slice), q = k-quarter 0..3.
// Each thread holds its 64 W_hh floats in registers (as 32 f32x2 pairs).
struct __align__(16) GruSmem {
    float HB[2][4][4][68];   // [parity][nn][q][64 + pad]  (h, padded for banks)
    float xs[4][516];        // input sequence per batch row (padded)
    float Gx[128][4];        // gate exchange: [0..31]=pr, [32..63]=pz, [64..95]=ghn, [96..127]=gin
    unsigned long long mbar[2];
};

__global__ void __cluster_dims__(8, 1, 1) __launch_bounds__(384, 1)
gru_kernel(const float* __restrict__ inputs,
           const float* __restrict__ w_ih, const float* __restrict__ w_hh,
           const float* __restrict__ b_ih, const float* __restrict__ b_hh)
{
    __shared__ GruSmem sm;

    const int tid = threadIdx.x;
    const int bc  = blockIdx.x;       // cluster rank / column slice
    const int gN  = blockIdx.y;
    const int dd  = blockIdx.z;
    const int rr  = tid >> 2;
    const int q   = tid & 3;
    const int rowG = dd * 768 + ((rr >> 5) << 8) + (bc << 5) + (rr & 31);

    cg::cluster_group cluster = cg::this_cluster();

    // ---- W_hh slice into registers (64 floats = 32 f32x2) ----
    unsigned long long w2[32];
    {
        const ulonglong2* wg = reinterpret_cast<const ulonglong2*>(w_hh + (size_t)rowG * 256 + q * 64);
#pragma unroll
        for (int i = 0; i < 16; ++i) { ulonglong2 t = wg[i]; w2[2 * i] = t.x; w2[2 * i + 1] = t.y; }
    }
    const float wihr = w_ih[rowG];
    const float bihr = b_ih[rowG];
    const float bhhr = b_hh[rowG];

    // inputs (t=0 slice): xs[nn][s] = inputs[n][s]
    for (int idx = tid; idx < 4 * 512; idx += 384) {
        int nn = idx >> 9, s = idx & 511;
        sm.xs[nn][s] = inputs[(gN * 4 + nn) * D_IN + s];
    }
    // h0 = 0 (parity 0 buffer)
    for (int idx = tid; idx < 4 * 4 * 68; idx += 384)
        (&sm.HB[0][0][0][0])[idx] = 0.f;

    const unsigned mb0 = (unsigned)__cvta_generic_to_shared(&sm.mbar[0]);
    const unsigned mb1 = (unsigned)__cvta_generic_to_shared(&sm.mbar[1]);
    if (tid == 0) { mbar_init(mb0, 32); mbar_init(mb1, 32); }
    __syncthreads();
    cluster.sync();   // all mbars init'd + h0 ready before any push

    const int bcq = bc >> 1;               // quarter of own slice
    const int bco = (bc & 1) * 32;         // offset within quarter
    int ph0 = 0, ph1 = 0;

    for (int t = 0; t < 512; ++t) {
        const int p = t & 1;
        const int s = dd ? (511 - t) : t;

        if (t > 0) {
            int curph = p ? ph1 : ph0;
            if (tid == 0) mbar_wait_cluster(p ? mb1 : mb0, (unsigned)curph);
            if (p) ph1 ^= 1; else ph0 ^= 1;
        }
        __syncthreads();

        // ---- matvec: gh_partial[nn] over this thread's k-quarter ----
        const float* hbase = &sm.HB[p][0][0][0];
        float part[4];
#pragma unroll
        for (int nn = 0; nn < 4; ++nn) {
            const ulonglong2* hq = reinterpret_cast<const ulonglong2*>(hbase + nn * 272 + q * 68);
            unsigned long long a0 = 0ull, a1 = 0ull;
#pragma unroll
            for (int kk = 0; kk < 16; ++kk) {
                ulonglong2 hv = hq[kk];
                a0 = ffma2(w2[2 * kk],     hv.x, a0);
                a1 = ffma2(w2[2 * kk + 1], hv.y, a1);
            }
            F2U u0, u1; u0.u = a0; u1.u = a1;
            part[nn] = (u0.f.x + u0.f.y) + (u1.f.x + u1.f.y);
        }

        // ---- butterfly: reduce over q, redistribute nn -> lane q ----
        const int qb = q & 1, qc = q >> 1;
        float keep_lo = qb ? part[1] : part[0];
        float send_lo = qb ? part[0] : part[1];
        float keep_hi = qb ? part[3] : part[2];
        float send_hi = qb ? part[2] : part[3];
        float s0 = keep_lo + __shfl_xor_sync(0xffffffffu, send_lo, 1);
        float s1 = keep_hi + __shfl_xor_sync(0xffffffffu, send_hi, 1);
        float mine = qc ? s1 : s0;
        float othr = qc ? s0 : s1;
        float gh = mine + __shfl_xor_sync(0xffffffffu, othr, 2) + bhhr;  // full gh for nn=q
        float gi = fmaf(sm.xs[q][s], wihr, bihr);

        if (rr < 64) sm.Gx[rr][q] = gh + gi;
        else { sm.Gx[rr][q] = gh; sm.Gx[rr + 32][q] = gi; }
        __syncthreads();

        // ---- gates + push (warps 0..3 = 128 threads = 4 n x 32 cols) ----
        if (tid < 128) {
            const int n2 = tid >> 5;
            const int i  = tid & 31;
            float pr  = sm.Gx[i][n2]      ;
            float pz  = sm.Gx[32 + i][n2] ;
            float ghn = sm.Gx[64 + i][n2] ;
            float gin = sm.Gx[96 + i][n2] ;
            float r = 1.f / (1.f + __expf(-pr));
            float z = 1.f / (1.f + __expf(-pz));
            float npre = fmaf(r, ghn, gin);
            float tn = 1.f - 2.f / (1.f + __expf(2.f * npre));
            const int colg = (bc << 5) + i;
            float hold = sm.HB[p][n2][bcq][bco + i];
            float hnew = fmaf(z, hold - tn, tn);   // (1-z)*tn + z*hold

            const int n = gN * 4 + n2;
            g_M[(size_t)n * M_PER_N + s * 512 + dd * 256 + colg] = hnew;

            if (t < 511) {
                unsigned laddr = (unsigned)__cvta_generic_to_shared(&sm.HB[p ^ 1][n2][bcq][bco + i]);
                unsigned lmbar = (p ^ 1) ? mb1 : mb0;
#pragma unroll
                for (int dst = 0; dst < 8; ++dst)
                    st_remote(laddr, (unsigned)dst, hnew);
                __syncwarp();
                if ((tid & 31) == 0) {
                    asm volatile("fence.acq_rel.cluster;" ::: "memory");
#pragma unroll
                    for (int dst = 0; dst < 8; ++dst)
                        arrive_remote(lmbar, (unsigned)dst);
                }
            } else {
                g_Mn[n * 512 + dd * 256 + colg] = hnew;
            }
        }
    }
    cluster.sync();   // no CTA exits while peers may still push into it
}

// ---------------- MLP kernel: grid (NB, 2) — y: 0=actor, 1=critic ----------------
__device__ __forceinline__ void layer4(const float* __restrict__ W, const float* __restrict__ B,
                                       const float* __restrict__ in, float* out, int indim)
{
    const int warp = threadIdx.x >> 5, lane = threadIdx.x & 31;
    for (int j0 = warp * 32; j0 < warp * 32 + 32; j0 += 4) {
        float a0 = 0.f, a1 = 0.f, a2 = 0.f, a3 = 0.f;
        const float* w = W + (size_t)j0 * indim;
        for (int k = lane; k < indim; k += 32) {
            float x = in[k];
            a0 = fmaf(__ldg(w + k),             x, a0);
            a1 = fmaf(__ldg(w + indim + k),     x, a1);
            a2 = fmaf(__ldg(w + 2 * indim + k), x, a2);
            a3 = fmaf(__ldg(w + 3 * indim + k), x, a3);
        }
#pragma unroll
        for (int o = 16; o; o >>= 1) {
            a0 += __shfl_down_sync(0xffffffffu, a0, o);
            a1 += __shfl_down_sync(0xffffffffu, a1, o);
            a2 += __shfl_down_sync(0xffffffffu, a2, o);
            a3 += __shfl_down_sync(0xffffffffu, a3, o);
        }
        if (lane == 0) {
            out[j0]     = fmaxf(a0 + B[j0],     0.f);
            out[j0 + 1] = fmaxf(a1 + B[j0 + 1], 0.f);
            out[j0 + 2] = fmaxf(a2 + B[j0 + 2], 0.f);
            out[j0 + 3] = fmaxf(a3 + B[j0 + 3], 0.f);
        }
    }
}

__global__ void __launch_bounds__(256)
mlp_kernel(const float* __restrict__ rnn,
           const float* __restrict__ aw0, const float* __restrict__ ab0,
           const float* __restrict__ aw1, const float* __restrict__ ab1,
           const float* __restrict__ alw, const float* __restrict__ alb,
           const float* __restrict__ cw0, const float* __restrict__ cb0,
           const float* __restrict__ cw1, const float* __restrict__ cb1,
           const float* __restrict__ cow, const float* __restrict__ cob)
{
    __shared__ float hn[1024], h1[256], h2[256];
    const int n = blockIdx.x, br = blockIdx.y, tid = threadIdx.x;
    const bool newep = (g_nonzero == 0);
    const float* hx = rnn + (size_t)n * TOTAL;
    int P = (int)hx[P_OFF];
    if (P < 0) P = 0; if (P > 511) P = 511;

    const float* w0 = br ? cw0 : aw0;  const float* b0 = br ? cb0 : ab0;
    const float* w1 = br ? cw1 : aw1;  const float* b1 = br ? cb1 : ab1;
    const float* wo = br ? cow : alw;  const float* bo = br ? cob : alb;

    // hn = [ Mn interleaved (h*2 + d), r = M[P][n][:] ]
    for (int k = tid; k < 1024; k += 256) {
        float v;
        if (k < 512) {
            int h = k >> 1, d2 = k & 1;
            v = newep ? g_Mn[n * 512 + d2 * 256 + h] : hx[MN_OFF + d2 * 256 + h];
        } else {
            int kk = k - 512;
            v = newep ? g_M[(size_t)n * M_PER_N + P * 512 + kk] : hx[M_OFF + P * 512 + kk];
        }
        hn[k] = v;
    }
    __syncthreads();

    layer4(w0, b0, hn, h1, 1024);
    __syncthreads();
    layer4(w1, b1, h1, h2, 256);
    __syncthreads();
    if (tid < 32) {
        float acc = 0.f;
        for (int k = tid; k < 256; k += 32) acc = fmaf(wo[k], h2[k], acc);
#pragma unroll
        for (int o = 16; o; o >>= 1) acc += __shfl_down_sync(0xffffffffu, acc, o);
        if (tid == 0) { if (br) g_v[n] = acc + bo[0]; else g_loc[n] = acc + bo[0]; }
    }
}

// ---------------- output fill kernel ----------------
// out is 9 t-slices of (NB, TOTAL): t=0..7 = hx_out, t=8 = hx_out[-1] (== t=7)
__global__ void __launch_bounds__(256)
fill_kernel(const float* __restrict__ inputs, const float* __restrict__ rnn,
            const float* __restrict__ eps, const float* __restrict__ logstd,
            float* __restrict__ out)
{
    int o = blockIdx.x * 256 + threadIdx.x;
    if (o >= TOTAL) return;
    const int t9 = blockIdx.y;
    const int n  = blockIdx.z;
    const int teff = (t9 < 8) ? t9 : 7;
    const float* hx = rnn + (size_t)n * TOTAL;
    const bool newep = (g_nonzero == 0);

    float val;
    if (o >= M_OFF) {
        if (o < MN_OFF) {
            int m = o - M_OFF;
            val = newep ? g_M[(size_t)n * M_PER_N + m] : hx[o];
        } else {
            val = newep ? g_Mn[n * 512 + (o - MN_OFF)] : hx[o];
        }
    } else if (o >= 4 && o < P_OFF) {
        val = hx[o];                         // hx_h passthrough
    } else if (o == P_OFF) {
        int P = (int)hx[P_OFF];
        val = (float)((P + 1) & 511);        // (P+1) % 512
    } else if (o == 0) {
        float act = inputs[(size_t)(teff * NB + n) * D_IN + (D_IN - 1)];
        float scale = expf(logstd[0]);
        val = (act < 0.f) ? fmaf(scale, eps[teff * NB + n], g_loc[n]) : act;
    } else if (o == 1) {
        val = g_loc[n];
    } else if (o == 2) {
        val = expf(logstd[0]);
    } else { // o == 3
        val = g_v[n];
    }
    out[(size_t)(t9 * NB + n) * TOTAL + o] = val;
}

// ---------------- launch ----------------
extern "C" void kernel_launch(void* const* d_in, const int* in_sizes, int n_in,
                              void* d_out, int out_size)
{
    const float* inputs = (const float*)d_in[0];
    const float* rnn    = (const float*)d_in[1];
    const float* eps    = (const float*)d_in[2];
    const float* gwih   = (const float*)d_in[3];
    const float* gwhh   = (const float*)d_in[4];
    const float* gbih   = (const float*)d_in[5];
    const float* gbhh   = (const float*)d_in[6];
    const float* aw0    = (const float*)d_in[7];
    const float* ab0    = (const float*)d_in[8];
    const float* aw1    = (const float*)d_in[9];
    const float* ab1    = (const float*)d_in[10];
    const float* alw    = (const float*)d_in[11];
    const float* alb    = (const float*)d_in[12];
    const float* alogstd= (const float*)d_in[13];
    const float* cw0    = (const float*)d_in[14];
    const float* cb0    = (const float*)d_in[15];
    const float* cw1    = (const float*)d_in[16];
    const float* cb1    = (const float*)d_in[17];
    const float* cow    = (const float*)d_in[18];
    const float* cob    = (const float*)d_in[19];
    float* out = (float*)d_out;

    (void)in_sizes; (void)n_in; (void)out_size;

    reset_flag_kernel<<<1, 1>>>();
    scan_flag_kernel<<<512, 256>>>(rnn);
    gru_kernel<<<dim3(8, 8, 2), 384>>>(inputs, gwih, gwhh, gbih, gbhh);
    mlp_kernel<<<dim3(NB, 2), 256>>>(rnn, aw0, ab0, aw1, ab1, alw, alb,
                                     cw0, cb0, cw1, cb1, cow, cob);
    fill_kernel<<<dim3((TOTAL + 255) / 256, 9, NB), 256>>>(inputs, rnn, eps, alogstd, out);
}

// round 8
// speedup vs baseline: 1.5150x; 1.5150x over previous
#include <cuda_runtime.h>
#include <cooperative_groups.h>
#include <math.h>

namespace cg = cooperative_groups;

// Problem constants
#define NB      32          // batch N
#define D_IN    513         // S+1
#define TOTAL   262917      // per-(t,n) output row length
#define P_OFF   260
#define M_OFF   261
#define MN_OFF  262405
#define M_PER_N 262144      // S * ND * H

// Scratch (device globals — no allocation allowed)
__device__ float g_M [NB * M_PER_N];   // [n][s*512 + d*256 + h]
__device__ float g_Mn[NB * 512];       // [n][d*256 + h]
__device__ float g_loc[NB];
__device__ float g_v  [NB];
__device__ int   g_nonzero;

// ---------------- f32x2 helper ----------------
__device__ __forceinline__ unsigned long long ffma2(unsigned long long a,
                                                    unsigned long long b,
                                                    unsigned long long c) {
    unsigned long long d;
    asm("fma.rn.f32x2 %0, %1, %2, %3;" : "=l"(d) : "l"(a), "l"(b), "l"(c));
    return d;
}
union F2U { unsigned long long u; float2 f; };

// ---------------- flag kernels ----------------
__global__ void reset_flag_kernel() { g_nonzero = 0; }

__global__ void scan_flag_kernel(const float* __restrict__ rnn) {
    const int NV4 = (NB * TOTAL) / 4;   // exact: 8413344/4
    const float4* p = reinterpret_cast<const float4*>(rnn);
    bool nz = false;
    for (int i = blockIdx.x * blockDim.x + threadIdx.x; i < NV4; i += gridDim.x * blockDim.x) {
        float4 v = p[i];
        nz |= (v.x != 0.f) | (v.y != 0.f) | (v.z != 0.f) | (v.w != 0.f);
    }
    if (__syncthreads_or(nz) && threadIdx.x == 0) atomicOr(&g_nonzero, 1);
}

// ---------------- GRU cluster kernel ----------------
// grid (8, 8, 2): x = cluster rank (32-col slice of h), y = n-group (4 n), z = direction.
// Sync scheme (R5, proven): per step, gates write own slice to double-buffered hbuf,
// cluster.sync, all CTAs pull all 8 slices via DSMEM float4 loads, __syncthreads.
// Math engine (R6, proven): W_hh slice in registers, fma.rn.f32x2 matvec,
// shfl butterfly to reduce over k-quarters while redistributing batch rows.
// Thread layout: tid = rr*4 + q; rr = gate row 0..95 within slice, q = k-quarter.
struct __align__(16) GruSmem {
    float Hw[4][4][68];      // [nn][q][64 + 4 pad]  full h for the 4 batch rows
    float hbuf[2][4][32];    // [parity][nn][i]  own 32-col slice of h_new
    float xs[4][512];        // input sequence per batch row
    float Gx[128][4];        // gate exchange: rows {pr,pz,ghn,gin} x [nn]
};

__global__ void __cluster_dims__(8, 1, 1) __launch_bounds__(384, 1)
gru_kernel(const float* __restrict__ inputs,
           const float* __restrict__ w_ih, const float* __restrict__ w_hh,
           const float* __restrict__ b_ih, const float* __restrict__ b_hh)
{
    __shared__ GruSmem sm;

    const int tid = threadIdx.x;
    const int bc  = blockIdx.x;       // cluster rank / column slice
    const int gN  = blockIdx.y;
    const int dd  = blockIdx.z;
    const int rr  = tid >> 2;
    const int q   = tid & 3;
    const int rowG = dd * 768 + ((rr >> 5) << 8) + (bc << 5) + (rr & 31);

    cg::cluster_group cluster = cg::this_cluster();

    // ---- W_hh slice into registers (64 floats = 32 f32x2) ----
    unsigned long long w2[32];
    {
        const ulonglong2* wg = reinterpret_cast<const ulonglong2*>(w_hh + (size_t)rowG * 256 + q * 64);
#pragma unroll
        for (int i = 0; i < 16; ++i) { ulonglong2 t = wg[i]; w2[2 * i] = t.x; w2[2 * i + 1] = t.y; }
    }
    const float wihr = w_ih[rowG];
    const float bihr = b_ih[rowG];
    const float bhhr = b_hh[rowG];

    // inputs: xs[nn][s] = inputs[0][n][s]
    for (int idx = tid; idx < 4 * 512; idx += 384) {
        int nn = idx >> 9, s = idx & 511;
        sm.xs[nn][s] = inputs[(gN * 4 + nn) * D_IN + s];
    }
    // h0 = 0
    for (int idx = tid; idx < 4 * 4 * 68; idx += 384)
        (&sm.Hw[0][0][0])[idx] = 0.f;
    __syncthreads();
    cluster.sync();

    const int bcq = bc >> 1;               // quarter index of own slice within Hw
    const int bco = (bc & 1) * 32;         // float offset within that quarter

    for (int t = 0; t < 512; ++t) {
        const int p = t & 1;
        const int s = dd ? (511 - t) : t;

        // ---- matvec: gh partial over this thread's k-quarter, all 4 batch rows ----
        float part[4];
#pragma unroll
        for (int nn = 0; nn < 4; ++nn) {
            const ulonglong2* hq = reinterpret_cast<const ulonglong2*>(&sm.Hw[nn][q][0]);
            unsigned long long a0 = 0ull, a1 = 0ull;
#pragma unroll
            for (int kk = 0; kk < 16; ++kk) {
                ulonglong2 hv = hq[kk];
                a0 = ffma2(w2[2 * kk],     hv.x, a0);
                a1 = ffma2(w2[2 * kk + 1], hv.y, a1);
            }
            F2U u0, u1; u0.u = a0; u1.u = a1;
            part[nn] = (u0.f.x + u0.f.y) + (u1.f.x + u1.f.y);
        }

        // ---- butterfly: reduce over q, redistribute nn -> lane q ----
        const int qb = q & 1, qc = q >> 1;
        float keep_lo = qb ? part[1] : part[0];
        float send_lo = qb ? part[0] : part[1];
        float keep_hi = qb ? part[3] : part[2];
        float send_hi = qb ? part[2] : part[3];
        float s0 = keep_lo + __shfl_xor_sync(0xffffffffu, send_lo, 1);
        float s1 = keep_hi + __shfl_xor_sync(0xffffffffu, send_hi, 1);
        float mine = qc ? s1 : s0;
        float othr = qc ? s0 : s1;
        float gh = mine + __shfl_xor_sync(0xffffffffu, othr, 2) + bhhr;  // full gh for nn=q
        float gi = fmaf(sm.xs[q][s], wihr, bihr);

        if (rr < 64) sm.Gx[rr][q] = gh + gi;
        else { sm.Gx[rr][q] = gh; sm.Gx[rr + 32][q] = gi; }
        __syncthreads();

        // ---- gates (warps 0..3 = 4 n x 32 cols), write own slice to hbuf ----
        if (tid < 128) {
            const int n2 = tid >> 5;
            const int i  = tid & 31;
            float pr  = sm.Gx[i][n2];
            float pz  = sm.Gx[32 + i][n2];
            float ghn = sm.Gx[64 + i][n2];
            float gin = sm.Gx[96 + i][n2];
            float r = 1.f / (1.f + __expf(-pr));
            float z = 1.f / (1.f + __expf(-pz));
            float npre = fmaf(r, ghn, gin);
            float tn = 1.f - 2.f / (1.f + __expf(2.f * npre));
            const int colg = (bc << 5) + i;
            float hold = sm.Hw[n2][bcq][bco + i];
            float hnew = fmaf(z, hold - tn, tn);   // (1-z)*tn + z*hold

            const int n = gN * 4 + n2;
            g_M[(size_t)n * M_PER_N + s * 512 + dd * 256 + colg] = hnew;
            sm.hbuf[p][n2][i] = hnew;
            if (t == 511)
                g_Mn[n * 512 + dd * 256 + colg] = hnew;
        }

        if (t < 511) {
            cluster.sync();
            // pull all 8 slices into Hw as float4 (256 loads, one round)
            if (tid < 256) {
                const int src = tid >> 5;
                const int rem = tid & 31;
                const int nn  = rem >> 3;
                const int i4  = rem & 7;
                const float* peer = cluster.map_shared_rank(&sm.hbuf[p][0][0], (unsigned)src);
                float4 v = reinterpret_cast<const float4*>(peer)[nn * 8 + i4];
                *reinterpret_cast<float4*>(&sm.Hw[nn][src >> 1][(src & 1) * 32 + i4 * 4]) = v;
            }
            __syncthreads();
        }
    }
    cluster.sync();   // no CTA exits while a peer may still read its hbuf
}

// ---------------- MLP kernel: grid (NB, 2) — y: 0=actor, 1=critic ----------------
__device__ __forceinline__ void layer4(const float* __restrict__ W, const float* __restrict__ B,
                                       const float* __restrict__ in, float* out, int indim)
{
    const int warp = threadIdx.x >> 5, lane = threadIdx.x & 31;
    const int nk4 = indim >> 2;
    const float4* in4 = reinterpret_cast<const float4*>(in);
    for (int j0 = warp * 32; j0 < warp * 32 + 32; j0 += 4) {
        const float4* w0 = reinterpret_cast<const float4*>(W + (size_t)j0 * indim);
        const float4* w1 = reinterpret_cast<const float4*>(W + (size_t)(j0 + 1) * indim);
        const float4* w2 = reinterpret_cast<const float4*>(W + (size_t)(j0 + 2) * indim);
        const float4* w3 = reinterpret_cast<const float4*>(W + (size_t)(j0 + 3) * indim);
        float a0 = 0.f, a1 = 0.f, a2 = 0.f, a3 = 0.f;
        for (int k = lane; k < nk4; k += 32) {
            float4 x = in4[k];
            float4 v0 = __ldg(w0 + k);
            float4 v1 = __ldg(w1 + k);
            float4 v2 = __ldg(w2 + k);
            float4 v3 = __ldg(w3 + k);
            a0 += v0.x * x.x + v0.y * x.y + v0.z * x.z + v0.w * x.w;
            a1 += v1.x * x.x + v1.y * x.y + v1.z * x.z + v1.w * x.w;
            a2 += v2.x * x.x + v2.y * x.y + v2.z * x.z + v2.w * x.w;
            a3 += v3.x * x.x + v3.y * x.y + v3.z * x.z + v3.w * x.w;
        }
#pragma unroll
        for (int o = 16; o; o >>= 1) {
            a0 += __shfl_down_sync(0xffffffffu, a0, o);
            a1 += __shfl_down_sync(0xffffffffu, a1, o);
            a2 += __shfl_down_sync(0xffffffffu, a2, o);
            a3 += __shfl_down_sync(0xffffffffu, a3, o);
        }
        if (lane == 0) {
            out[j0]     = fmaxf(a0 + B[j0],     0.f);
            out[j0 + 1] = fmaxf(a1 + B[j0 + 1], 0.f);
            out[j0 + 2] = fmaxf(a2 + B[j0 + 2], 0.f);
            out[j0 + 3] = fmaxf(a3 + B[j0 + 3], 0.f);
        }
    }
}

__global__ void __launch_bounds__(256)
mlp_kernel(const float* __restrict__ rnn,
           const float* __restrict__ aw0, const float* __restrict__ ab0,
           const float* __restrict__ aw1, const float* __restrict__ ab1,
           const float* __restrict__ alw, const float* __restrict__ alb,
           const float* __restrict__ cw0, const float* __restrict__ cb0,
           const float* __restrict__ cw1, const float* __restrict__ cb1,
           const float* __restrict__ cow, const float* __restrict__ cob)
{
    __shared__ __align__(16) float hn[1024];
    __shared__ __align__(16) float h1[256];
    __shared__ __align__(16) float h2[256];
    const int n = blockIdx.x, br = blockIdx.y, tid = threadIdx.x;
    const bool newep = (g_nonzero == 0);
    const float* hx = rnn + (size_t)n * TOTAL;
    int P = (int)hx[P_OFF];
    if (P < 0) P = 0; if (P > 511) P = 511;

    const float* w0 = br ? cw0 : aw0;  const float* b0 = br ? cb0 : ab0;
    const float* w1 = br ? cw1 : aw1;  const float* b1 = br ? cb1 : ab1;
    const float* wo = br ? cow : alw;  const float* bo = br ? cob : alb;

    // hn = [ Mn interleaved (h*2 + d), r = M[P][n][:] ]
    for (int k = tid; k < 1024; k += 256) {
        float v;
        if (k < 512) {
            int h = k >> 1, d2 = k & 1;
            v = newep ? g_Mn[n * 512 + d2 * 256 + h] : hx[MN_OFF + d2 * 256 + h];
        } else {
            int kk = k - 512;
            v = newep ? g_M[(size_t)n * M_PER_N + P * 512 + kk] : hx[M_OFF + P * 512 + kk];
        }
        hn[k] = v;
    }
    __syncthreads();

    layer4(w0, b0, hn, h1, 1024);
    __syncthreads();
    layer4(w1, b1, h1, h2, 256);
    __syncthreads();
    if (tid < 32) {
        float acc = 0.f;
        for (int k = tid; k < 256; k += 32) acc = fmaf(wo[k], h2[k], acc);
#pragma unroll
        for (int o = 16; o; o >>= 1) acc += __shfl_down_sync(0xffffffffu, acc, o);
        if (tid == 0) { if (br) g_v[n] = acc + bo[0]; else g_loc[n] = acc + bo[0]; }
    }
}

// ---------------- output fill kernel ----------------
// out is 9 t-slices of (NB, TOTAL): t=0..7 = hx_out, t=8 = hx_out[-1] (== t=7)
__global__ void __launch_bounds__(256)
fill_kernel(const float* __restrict__ inputs, const float* __restrict__ rnn,
            const float* __restrict__ eps, const float* __restrict__ logstd,
            float* __restrict__ out)
{
    int o = blockIdx.x * 256 + threadIdx.x;
    if (o >= TOTAL) return;
    const int t9 = blockIdx.y;
    const int n  = blockIdx.z;
    const int teff = (t9 < 8) ? t9 : 7;
    const float* hx = rnn + (size_t)n * TOTAL;
    const bool newep = (g_nonzero == 0);

    float val;
    if (o >= M_OFF) {
        if (o < MN_OFF) {
            int m = o - M_OFF;
            val = newep ? g_M[(size_t)n * M_PER_N + m] : hx[o];
        } else {
            val = newep ? g_Mn[n * 512 + (o - MN_OFF)] : hx[o];
        }
    } else if (o >= 4 && o < P_OFF) {
        val = hx[o];                         // hx_h passthrough
    } else if (o == P_OFF) {
        int P = (int)hx[P_OFF];
        val = (float)((P + 1) & 511);        // (P+1) % 512
    } else if (o == 0) {
        float act = inputs[(size_t)(teff * NB + n) * D_IN + (D_IN - 1)];
        float scale = expf(logstd[0]);
        val = (act < 0.f) ? fmaf(scale, eps[teff * NB + n], g_loc[n]) : act;
    } else if (o == 1) {
        val = g_loc[n];
    } else if (o == 2) {
        val = expf(logstd[0]);
    } else { // o == 3
        val = g_v[n];
    }
    out[(size_t)(t9 * NB + n) * TOTAL + o] = val;
}

// ---------------- launch ----------------
extern "C" void kernel_launch(void* const* d_in, const int* in_sizes, int n_in,
                              void* d_out, int out_size)
{
    const float* inputs = (const float*)d_in[0];
    const float* rnn    = (const float*)d_in[1];
    const float* eps    = (const float*)d_in[2];
    const float* gwih   = (const float*)d_in[3];
    const float* gwhh   = (const float*)d_in[4];
    const float* gbih   = (const float*)d_in[5];
    const float* gbhh   = (const float*)d_in[6];
    const float* aw0    = (const float*)d_in[7];
    const float* ab0    = (const float*)d_in[8];
    const float* aw1    = (const float*)d_in[9];
    const float* ab1    = (const float*)d_in[10];
    const float* alw    = (const float*)d_in[11];
    const float* alb    = (const float*)d_in[12];
    const float* alogstd= (const float*)d_in[13];
    const float* cw0    = (const float*)d_in[14];
    const float* cb0    = (const float*)d_in[15];
    const float* cw1    = (const float*)d_in[16];
    const float* cb1    = (const float*)d_in[17];
    const float* cow    = (const float*)d_in[18];
    const float* cob    = (const float*)d_in[19];
    float* out = (float*)d_out;

    (void)in_sizes; (void)n_in; (void)out_size;

    reset_flag_kernel<<<1, 1>>>();
    scan_flag_kernel<<<512, 256>>>(rnn);
    gru_kernel<<<dim3(8, 8, 2), 384>>>(inputs, gwih, gwhh, gbih, gbhh);
    mlp_kernel<<<dim3(NB, 2), 256>>>(rnn, aw0, ab0, aw1, ab1, alw, alb,
                                     cw0, cb0, cw1, cb1, cow, cob);
    fill_kernel<<<dim3((TOTAL + 255) / 256, 9, NB), 256>>>(inputs, rnn, eps, alogstd, out);
}